// round 13
// baseline (speedup 1.0000x reference)
#include <cuda_runtime.h>
#include <cstdint>

// ExtractTensorPatches: x (4,32,256,256) f32 -> out (4,961,32,16,16) f32
// out[b,l,c,i,j] = x[b,c,oh*8+i,ow*8+j] + EPS * patch_sum(b,c,oh,ow)
// l = oh*31 + ow.
//
// One CTA per (b,c,oh): 16x256 band staged in smem, patch sums via two-level
// reduction; each 1KB output patch is assembled in a smem staging buffer and
// written with cp.async.bulk (async-proxy store engine, 1KB bursts, bypasses
// the L1/LSU store path).

#define CHAN   32
#define HW     256
#define WIN    16
#define STR    8
#define HO     31
#define WO     31
#define LPATCH (HO * WO)       // 961
#define TPAD   272             // rows i/i+1 hit disjoint bank halves

__device__ __forceinline__ float4 ld4g(const float* p) {
    return *reinterpret_cast<const float4*>(p);
}

__global__ __launch_bounds__(256)
void extract_patches_kernel(const float* __restrict__ x, float* __restrict__ out) {
    const float EPS = 1e-6f;

    __shared__ float tile[WIN][TPAD];            // 16 rows x 256 (+16 pad)
    __shared__ float part[64][5];
    __shared__ float colsum4[64];
    __shared__ float psum[WO + 1];
    __shared__ __align__(16) float stage[WO][256];  // 31 x 1KB staged patches

    int bx = blockIdx.x;
    int oh = bx % HO;
    int c  = (bx / HO) & (CHAN - 1);
    int b  = bx / (HO * CHAN);

    int tid  = threadIdx.x;
    int wid  = tid >> 5;
    int lane = tid & 31;

    const float* src = x + ((size_t)(b * CHAN + c) * HW + (size_t)(oh * STR)) * HW;

    // ---- Phase 1: load 16x256 band (4 float4/thread), per-thread partial.
    int col4 = tid & 63;
    int r0   = tid >> 6;
    float acc = 0.f;
    #pragma unroll
    for (int k = 0; k < 4; k++) {
        int r = r0 + 4 * k;
        float4 v = ld4g(src + (size_t)r * HW + col4 * 4);
        acc += v.x + v.y + v.z + v.w;
        *reinterpret_cast<float4*>(&tile[r][col4 * 4]) = v;
    }
    part[col4][r0] = acc;
    __syncthreads();

    // ---- Phase 2: column-group sums over all 16 rows (threads 0..63)
    if (tid < 64) {
        colsum4[tid] = part[tid][0] + part[tid][1] + part[tid][2] + part[tid][3];
    }
    __syncthreads();

    // ---- Phase 3: patch sums (threads 0..30)
    if (tid < WO) {
        int g0 = 2 * tid;
        psum[tid] = colsum4[g0] + colsum4[g0 + 1] + colsum4[g0 + 2] + colsum4[g0 + 3];
    }
    __syncthreads();

    // ---- Phase 4: warp w owns patches p = w, w+8, ... Assemble patch in
    // staging smem, then elected lane issues a 1KB bulk async store.
    size_t out_base = (((size_t)b * LPATCH + (size_t)oh * WO) * CHAN + c) * (size_t)(WIN * WIN);
    for (int p = wid; p < WO; p += 8) {
        float e = EPS * psum[p];
        #pragma unroll
        for (int h = 0; h < 2; h++) {
            int q = lane + 32 * h;       // float4 index within patch
            int i = q >> 2;
            int s = q & 3;
            float4 v = *reinterpret_cast<const float4*>(&tile[i][p * STR + s * 4]);
            v.x += e; v.y += e; v.z += e; v.w += e;
            *reinterpret_cast<float4*>(&stage[p][q * 4]) = v;
        }
        __syncwarp();
        if (lane == 0) {
            asm volatile("fence.proxy.async.shared::cta;" ::: "memory");
            uint32_t saddr = (uint32_t)__cvta_generic_to_shared(&stage[p][0]);
            const float* gdst = out + out_base + (size_t)p * (CHAN * WIN * WIN);
            asm volatile("cp.async.bulk.global.shared::cta.bulk_group [%0], [%1], %2;"
                         :: "l"(gdst), "r"(saddr), "n"(1024) : "memory");
        }
    }
    if (lane == 0) {
        asm volatile("cp.async.bulk.commit_group;" ::: "memory");
        asm volatile("cp.async.bulk.wait_group 0;" ::: "memory");
    }
}

extern "C" void kernel_launch(void* const* d_in, const int* in_sizes, int n_in,
                              void* d_out, int out_size) {
    const float* x = (const float*)d_in[0];
    float* out = (float*)d_out;

    dim3 grid(4 * CHAN * HO);   // 3968 CTAs: one per (b, c, oh)
    dim3 block(256);
    extract_patches_kernel<<<grid, block>>>(x, out);
}

// round 14
// speedup vs baseline: 1.2869x; 1.2869x over previous
#include <cuda_runtime.h>

// ExtractTensorPatches: x (4,32,256,256) f32 -> out (4,961,32,16,16) f32
// out[b,l,c,i,j] = x[b,c,oh*8+i,ow*8+j] + EPS * patch_sum(b,c,oh,ow)
// l = oh*31 + ow.
//
// FINAL (verified twice at 27.1us): one CTA per (b,c,oh); 16x256 band staged
// in smem (conflict-free row stride 272), patch sums via two-level smem
// reduction, 31 patches streamed out as evict-first float4 stores.
//
// Eleven structural variants (read dedup, persistence+double-buffer, burst
// shaping, grid order, L2 eviction policies, 256-bit stores, write-through,
// TMA bulk stores, register-resident gather) all pin at or above 27.1us:
// this kernel sits on the compulsory-traffic DRAM floor (126MB write +
// 33.5MB read per iteration ~= 5.9 TB/s sustained mixed HBM traffic).

#define CHAN   32
#define HW     256
#define WIN    16
#define STR    8
#define HO     31
#define WO     31
#define LPATCH (HO * WO)       // 961
#define TPAD   272             // 256 + 16 pad: rows i/i+1 hit disjoint bank halves

__device__ __forceinline__ float4 ld4g(const float* p) {
    return *reinterpret_cast<const float4*>(p);
}

__global__ __launch_bounds__(256)
void extract_patches_kernel(const float* __restrict__ x, float* __restrict__ out) {
    const float EPS = 1e-6f;

    __shared__ float tile[WIN][TPAD];     // 16 rows x 256 (+16 pad) floats
    __shared__ float part[64][5];         // per-(col4, row-group) partials (pad 5)
    __shared__ float colsum4[64];         // sum over 16 rows of each 4-col group
    __shared__ float psum[WO + 1];        // 31 patch sums

    int bx = blockIdx.x;
    int oh = bx % HO;
    int c  = (bx / HO) & (CHAN - 1);
    int b  = bx / (HO * CHAN);

    int tid  = threadIdx.x;
    int wid  = tid >> 5;
    int lane = tid & 31;

    const float* src = x + ((size_t)(b * CHAN + c) * HW + (size_t)(oh * STR)) * HW;

    // ---- Phase 1: load 16x256 band (1024 float4s; 4 per thread), accumulate
    // per-thread partial sum. Thread covers fixed col4 = tid&63, rows r0+{0,4,8,12}.
    int col4 = tid & 63;
    int r0   = tid >> 6;
    float acc = 0.f;
    #pragma unroll
    for (int k = 0; k < 4; k++) {
        int r = r0 + 4 * k;
        float4 v = ld4g(src + (size_t)r * HW + col4 * 4);
        acc += v.x + v.y + v.z + v.w;
        *reinterpret_cast<float4*>(&tile[r][col4 * 4]) = v;
    }
    part[col4][r0] = acc;
    __syncthreads();

    // ---- Phase 2: column-group sums over all 16 rows (threads 0..63)
    if (tid < 64) {
        colsum4[tid] = part[tid][0] + part[tid][1] + part[tid][2] + part[tid][3];
    }
    __syncthreads();

    // ---- Phase 3: patch sums (threads 0..30): window = 4 consecutive 4-col
    // groups starting at group 2*ow.
    if (tid < WO) {
        int g0 = 2 * tid;
        psum[tid] = colsum4[g0] + colsum4[g0 + 1] + colsum4[g0 + 2] + colsum4[g0 + 3];
    }
    __syncthreads();

    // ---- Phase 4: 62 tasks (31 patches x 2 half-patches of 512B each),
    // flat-distributed over 8 warps. Streaming (evict-first) stores.
    size_t out_base = (((size_t)b * LPATCH + (size_t)oh * WO) * CHAN + c) * (size_t)(WIN * WIN);
    #pragma unroll
    for (int t = wid; t < 62; t += 8) {
        int p = t >> 1;            // patch ow
        int h = t & 1;             // half of patch
        int q = lane + 32 * h;     // float4 index within patch, 0..63
        int i = q >> 2;            // patch row
        int s = q & 3;             // 4-float segment within row

        float4 v = *reinterpret_cast<const float4*>(&tile[i][p * STR + s * 4]);
        float e = EPS * psum[p];
        v.x += e; v.y += e; v.z += e; v.w += e;

        float* dst = out + out_base + (size_t)p * (CHAN * WIN * WIN) + q * 4;
        __stcs(reinterpret_cast<float4*>(dst), v);
    }
}

extern "C" void kernel_launch(void* const* d_in, const int* in_sizes, int n_in,
                              void* d_out, int out_size) {
    const float* x = (const float*)d_in[0];
    float* out = (float*)d_out;

    dim3 grid(4 * CHAN * HO);   // 3968 CTAs: one per (b, c, oh)
    dim3 block(256);
    extract_patches_kernel<<<grid, block>>>(x, out);
}